// round 15
// baseline (speedup 1.0000x reference)
#include <cuda_runtime.h>
#include <cuda_fp16.h>
#include <cstdint>

#define NN 50000
#define NE 1600000
#define IND 128
#define HD 64
#define NR 5
#define SA_STRIDE 68
#define NEG_SLOPE 0.01f
#define NCHUNK 196   // ceil(50000/256)
#define TBX 391      // ceil(50000/128) tensor row tiles
#define HB 1563      // ceil(NE/1024) hist/fill blocks (4 edges/thread)

// ---- scratch (device globals; no allocation allowed) ----
__device__ float g_S[NN * NR];
__device__ int   g_deg[NN];
__device__ int   g_off[NN + 1];
__device__ int   g_part[256];
__device__ int   g_cur[NN];
__device__ int2  g_cpack[NE];     // {src | (r<<16), bits(w)}
__device__ float g_emb0[NN * HD];
__device__ float g_emb1[NN * HD];
__device__ float g_emb2[NN * HD];
__device__ __half g_T[(size_t)10 * NN * HD];  // fp16: TA_r (0..4), TB_r (5+r); 64 MB

// ---------------------------------------------------------------------------
// tf32 helpers (validated R3/R8)
__device__ __forceinline__ uint32_t f2tf(float f) {
  uint32_t r;
  asm("cvt.rna.tf32.f32 %0, %1;" : "=r"(r) : "f"(f));
  return r;
}
__device__ __forceinline__ void split_tf(float f, uint32_t& hi, uint32_t& lo) {
  hi = f2tf(f);
  lo = f2tf(f - __uint_as_float(hi));
}
__device__ __forceinline__ void mma_tf32(float c[4], uint32_t a0, uint32_t a1,
                                         uint32_t a2, uint32_t a3,
                                         uint32_t b0, uint32_t b1) {
  asm volatile(
      "mma.sync.aligned.m16n8k8.row.col.f32.tf32.tf32.f32 "
      "{%0,%1,%2,%3}, {%4,%5,%6,%7}, {%8,%9}, {%0,%1,%2,%3};"
      : "+f"(c[0]), "+f"(c[1]), "+f"(c[2]), "+f"(c[3])
      : "r"(a0), "r"(a1), "r"(a2), "r"(a3), "r"(b0), "r"(b1));
}

#define TRANS_SMEM (128 * SA_STRIDE * 4 + 8 * 8 * 32 * 16)  // 67584

// Shared tile routine (validated R8/R11).
__device__ __forceinline__ void tile_fill_mma(
    const float* __restrict__ Abase, int Kstride, int kofs, int row0,
    const float* __restrict__ W,
    float* sA, uint4* sBf, float acc[8][4],
    int tid, int lane, int warp) {
  int g = lane >> 2, tg = lane & 3;
  #pragma unroll 1
  for (int i = tid; i < 128 * 16; i += 256) {
    int r = i >> 4, c = i & 15;
    float4 v = make_float4(0.f, 0.f, 0.f, 0.f);
    if (row0 + r < NN)
      v = *(const float4*)(Abase + (size_t)(row0 + r) * Kstride + kofs + c * 4);
    *(float4*)(sA + r * SA_STRIDE + c * 4) = v;
  }
  #pragma unroll 1
  for (int s = tid; s < 8 * 8 * 32; s += 256) {
    int ks = s >> 8;
    int nc = (s >> 5) & 7;
    int ln = s & 31;
    int lg = ln >> 2, ltg = ln & 3;
    int k1 = ks * 8 + ltg, k2 = k1 + 4;
    int n = nc * 8 + lg;
    uint32_t h1, l1, h2, l2;
    split_tf(__ldg(&W[k1 * HD + n]), h1, l1);
    split_tf(__ldg(&W[k2 * HD + n]), h2, l2);
    sBf[s] = make_uint4(h1, h2, l1, l2);
  }
  __syncthreads();

  int wrow = warp * 16;
  #pragma unroll 1
  for (int ks = 0; ks < 8; ks++) {
    int kb = ks * 8;
    float af0 = sA[(wrow + g) * SA_STRIDE + kb + tg];
    float af1 = sA[(wrow + g + 8) * SA_STRIDE + kb + tg];
    float af2 = sA[(wrow + g) * SA_STRIDE + kb + tg + 4];
    float af3 = sA[(wrow + g + 8) * SA_STRIDE + kb + tg + 4];
    uint32_t ah0, al0, ah1, al1, ah2, al2, ah3, al3;
    split_tf(af0, ah0, al0);
    split_tf(af1, ah1, al1);
    split_tf(af2, ah2, al2);
    split_tf(af3, ah3, al3);
    const uint4* bp = sBf + ks * 8 * 32 + lane;
    #pragma unroll
    for (int nc = 0; nc < 8; nc++) {
      uint4 b = bp[nc * 32];
      mma_tf32(acc[nc], ah0, ah1, ah2, ah3, b.x, b.y);
      mma_tf32(acc[nc], ah0, ah1, ah2, ah3, b.z, b.w);
      mma_tf32(acc[nc], al0, al1, al2, al3, b.x, b.y);
    }
  }
}

// trans body: T[idx] = emb @ W_slice, fp16 writeback (validated R11).
__device__ __forceinline__ void trans_body(const float* __restrict__ relW,
                                           const float* __restrict__ emb,
                                           int idx, int bx, char* smraw) {
  float* sA = (float*)smraw;
  uint4* sBf = (uint4*)(smraw + 128 * SA_STRIDE * 4);
  int rr = idx % 5, half = idx / 5;
  const float* W = relW + ((size_t)rr * (2 * HD) + half * HD) * HD;

  int tid = threadIdx.x;
  int lane = tid & 31, warp = tid >> 5;
  int g = lane >> 2, tg = lane & 3;
  int row0 = bx * 128;

  float acc[8][4] = {};
  tile_fill_mma(emb, HD, 0, row0, W, sA, sBf, acc, tid, lane, warp);

  __half* out = g_T + (size_t)idx * NN * HD;
  int ra = row0 + warp * 16 + g;
  int rb = ra + 8;
  #pragma unroll
  for (int nc = 0; nc < 8; nc++) {
    int col = nc * 8 + 2 * tg;
    if (ra < NN)
      *(__half2*)(out + (size_t)ra * HD + col) = __floats2half2_rn(acc[nc][0], acc[nc][1]);
    if (rb < NN)
      *(__half2*)(out + (size_t)rb * HD + col) = __floats2half2_rn(acc[nc][2], acc[nc][3]);
  }
}

// ---------------------------------------------------------------------------
// K_pre: blocks [0,HB) -> edge histogram (4 edges/thread); [HB, HB+TBX) -> emb0.
__global__ void __launch_bounds__(256) k_pre(
    const float* __restrict__ etime, const int* __restrict__ eidx,
    const int* __restrict__ etype, const float* __restrict__ plam,
    const float* __restrict__ pbeta,
    const float* __restrict__ x, const float* __restrict__ fW,
    const float* __restrict__ fb) {
  extern __shared__ __align__(16) char smraw[];
  if (blockIdx.x < HB) {
    float lam = plam[0], beta = pbeta[0];
    int e0 = blockIdx.x * 1024 + threadIdx.x;
    #pragma unroll
    for (int k = 0; k < 4; k++) {
      int e = e0 + k * 256;
      if (e < NE) {
        float w = lam * expf(-beta * fabsf(__ldg(&etime[e])));
        int d = __ldg(&eidx[NE + e]);
        int r = __ldg(&etype[e]);
        atomicAdd(&g_S[d * NR + r], w);
        atomicAdd(&g_deg[d], 1);
      }
    }
    return;
  }
  // emb0 = x @ field_W + field_b (two k-halves)
  float* sA = (float*)smraw;
  uint4* sBf = (uint4*)(smraw + 128 * SA_STRIDE * 4);
  int tid = threadIdx.x;
  int lane = tid & 31, warp = tid >> 5;
  int g = lane >> 2, tg = lane & 3;
  int row0 = (blockIdx.x - HB) * 128;

  float acc[8][4] = {};
  tile_fill_mma(x, IND, 0, row0, fW, sA, sBf, acc, tid, lane, warp);
  __syncthreads();
  tile_fill_mma(x, IND, 64, row0, fW + (size_t)64 * HD, sA, sBf, acc, tid, lane, warp);

  int ra = row0 + warp * 16 + g;
  int rb = ra + 8;
  #pragma unroll
  for (int nc = 0; nc < 8; nc++) {
    int col = nc * 8 + 2 * tg;
    float b0 = __ldg(&fb[col]), b1 = __ldg(&fb[col + 1]);
    if (ra < NN)
      *(float2*)(g_emb0 + (size_t)ra * HD + col) =
          make_float2(acc[nc][0] + b0, acc[nc][1] + b1);
    if (rb < NN)
      *(float2*)(g_emb0 + (size_t)rb * HD + col) =
          make_float2(acc[nc][2] + b0, acc[nc][3] + b1);
  }
}

// ---------------------------------------------------------------------------
__global__ void k_scanA() {
  __shared__ int s[256];
  int tid = threadIdx.x;
  int i = blockIdx.x * 256 + tid;
  int v = (i < NN) ? g_deg[i] : 0;
  s[tid] = v;
  __syncthreads();
  #pragma unroll
  for (int d = 1; d < 256; d <<= 1) {
    int t = (tid >= d) ? s[tid - d] : 0;
    __syncthreads();
    s[tid] += t;
    __syncthreads();
  }
  if (i < NN) g_off[i] = s[tid] - v;
  if (tid == 255) g_part[blockIdx.x] = s[255];
}

__global__ void k_scanB() {
  __shared__ int s[256];
  int tid = threadIdx.x;
  int v = (tid < NCHUNK) ? g_part[tid] : 0;
  s[tid] = v;
  __syncthreads();
  #pragma unroll
  for (int d = 1; d < 256; d <<= 1) {
    int t = (tid >= d) ? s[tid - d] : 0;
    __syncthreads();
    s[tid] += t;
    __syncthreads();
  }
  if (tid < NCHUNK) g_part[tid] = s[tid] - v;
}

__global__ void k_scanC() {
  int i = blockIdx.x * 256 + threadIdx.x;
  if (i < NN) {
    int o = g_off[i] + g_part[i >> 8];
    g_off[i] = o;
    g_cur[i] = o;
  }
  if (i == 0) g_off[NN] = NE;
}

// ---------------------------------------------------------------------------
// K_mid: blocks [0,HB) -> CSR fill (4 edges/thread, int2 pack, recompute w);
//        blocks [HB, HB+10*TBX) -> trans layer-1 GEMMs.
__global__ void __launch_bounds__(256) k_mid(
    const int* __restrict__ eidx, const int* __restrict__ etype,
    const float* __restrict__ etime, const float* __restrict__ plam,
    const float* __restrict__ pbeta,
    const float* __restrict__ relW) {
  extern __shared__ __align__(16) char smraw[];
  if (blockIdx.x < HB) {
    float lam = plam[0], beta = pbeta[0];
    int e0 = blockIdx.x * 1024 + threadIdx.x;
    #pragma unroll
    for (int k = 0; k < 4; k++) {
      int e = e0 + k * 256;
      if (e < NE) {
        int d = __ldg(&eidx[NE + e]);
        float w = lam * expf(-beta * fabsf(__ldg(&etime[e])));
        int pos = atomicAdd(&g_cur[d], 1);
        g_cpack[pos] = make_int2(__ldg(&eidx[e]) | (__ldg(&etype[e]) << 16),
                                 __float_as_int(w));
      }
    }
    return;
  }
  int t = blockIdx.x - HB;
  trans_body(relW, g_emb0, t / TBX, t % TBX, smraw);
}

// Layer-2 trans (no merge partner).
__global__ void __launch_bounds__(256) k_trans2(const float* __restrict__ relW) {
  extern __shared__ __align__(16) char smraw[];
  trans_body(relW, g_emb1, blockIdx.y, blockIdx.x, smraw);
}

// ---------------------------------------------------------------------------
// CSR edge pass fused with dst-term. One warp/node; 4 edge-groups x 8 lanes,
// each lane owns 16 B (uint4 = 8 halves) of the 128 B row -> one warp-level
// row-load instruction covers 4 edges (vs 2 in the 16-lane shape).
__global__ void __launch_bounds__(256) k_edge_csr(const float* __restrict__ relb, int layer) {
  int node = (blockIdx.x * 256 + threadIdx.x) >> 5;
  if (node >= NN) return;
  int lane = threadIdx.x & 31;
  int grp = lane >> 3, fl = lane & 7;

  int beg = __ldg(&g_off[node]);
  int end = __ldg(&g_off[node + 1]);

  float a[8] = {};
  #pragma unroll 4
  for (int j = beg + grp; j < end; j += 4) {
    int2 p = __ldg(&g_cpack[j]);
    int src = p.x & 0xFFFF;
    int r = p.x >> 16;
    float w = __int_as_float(p.y);
    const uint4* rowp = (const uint4*)(g_T + ((size_t)r * NN + src) * HD);
    uint4 raw = __ldg(rowp + fl);
    float2 f0 = __half22float2(*(__half2*)&raw.x);
    float2 f1 = __half22float2(*(__half2*)&raw.y);
    float2 f2 = __half22float2(*(__half2*)&raw.z);
    float2 f3 = __half22float2(*(__half2*)&raw.w);
    a[0] += w * f0.x; a[1] += w * f0.y;
    a[2] += w * f1.x; a[3] += w * f1.y;
    a[4] += w * f2.x; a[5] += w * f2.y;
    a[6] += w * f3.x; a[7] += w * f3.y;
  }
  #pragma unroll
  for (int i = 0; i < 8; i++) {
    a[i] += __shfl_xor_sync(0xFFFFFFFF, a[i], 8);
    a[i] += __shfl_xor_sync(0xFFFFFFFF, a[i], 16);
  }

  if (grp == 0) {
    #pragma unroll
    for (int r = 0; r < NR; r++) {
      float s = __ldg(&g_S[node * NR + r]);
      const uint4* tp = (const uint4*)(g_T + ((size_t)(5 + r) * NN + node) * HD);
      uint4 raw = __ldg(tp + fl);
      float2 t0 = __half22float2(*(__half2*)&raw.x);
      float2 t1 = __half22float2(*(__half2*)&raw.y);
      float2 t2 = __half22float2(*(__half2*)&raw.z);
      float2 t3 = __half22float2(*(__half2*)&raw.w);
      const float4* bp = (const float4*)(relb + r * HD) + fl * 2;
      float4 b0 = __ldg(bp), b1 = __ldg(bp + 1);
      a[0] += s * (t0.x + b0.x); a[1] += s * (t0.y + b0.y);
      a[2] += s * (t1.x + b0.z); a[3] += s * (t1.y + b0.w);
      a[4] += s * (t2.x + b1.x); a[5] += s * (t2.y + b1.y);
      a[6] += s * (t3.x + b1.z); a[7] += s * (t3.y + b1.w);
    }
    float* emb = (layer == 0) ? g_emb1 : g_emb2;
    *(float4*)(emb + (size_t)node * HD + fl * 8) = make_float4(a[0], a[1], a[2], a[3]);
    *(float4*)(emb + (size_t)node * HD + fl * 8 + 4) = make_float4(a[4], a[5], a[6], a[7]);
  }
}

// out = sum_j leaky_relu(emb_j @ outW_j + outb_j), fused j-loop.
__global__ void __launch_bounds__(256) k_out_mma(
    const float* __restrict__ W0, const float* __restrict__ b0,
    const float* __restrict__ W1, const float* __restrict__ b1,
    const float* __restrict__ W2, const float* __restrict__ b2,
    float* __restrict__ out) {
  extern __shared__ __align__(16) char smraw[];
  float* sA = (float*)smraw;
  uint4* sBf = (uint4*)(smraw + 128 * SA_STRIDE * 4);

  int tid = threadIdx.x;
  int lane = tid & 31, warp = tid >> 5;
  int g = lane >> 2, tg = lane & 3;
  int row0 = blockIdx.x * 128;

  float o[8][4] = {};
  #pragma unroll 1
  for (int j = 0; j < 3; j++) {
    const float* emb = (j == 0) ? g_emb0 : (j == 1) ? g_emb1 : g_emb2;
    const float* W = (j == 0) ? W0 : (j == 1) ? W1 : W2;
    const float* b = (j == 0) ? b0 : (j == 1) ? b1 : b2;
    if (j) __syncthreads();
    float acc[8][4] = {};
    tile_fill_mma(emb, HD, 0, row0, W, sA, sBf, acc, tid, lane, warp);
    #pragma unroll
    for (int nc = 0; nc < 8; nc++) {
      int col = nc * 8 + 2 * tg;
      float bb0 = __ldg(&b[col]), bb1 = __ldg(&b[col + 1]);
      float z;
      z = acc[nc][0] + bb0; o[nc][0] += (z >= 0.f) ? z : NEG_SLOPE * z;
      z = acc[nc][1] + bb1; o[nc][1] += (z >= 0.f) ? z : NEG_SLOPE * z;
      z = acc[nc][2] + bb0; o[nc][2] += (z >= 0.f) ? z : NEG_SLOPE * z;
      z = acc[nc][3] + bb1; o[nc][3] += (z >= 0.f) ? z : NEG_SLOPE * z;
    }
  }

  int ra = row0 + warp * 16 + g;
  int rb = ra + 8;
  #pragma unroll
  for (int nc = 0; nc < 8; nc++) {
    int col = nc * 8 + 2 * tg;
    if (ra < NN)
      *(float2*)(out + (size_t)ra * HD + col) = make_float2(o[nc][0], o[nc][1]);
    if (rb < NN)
      *(float2*)(out + (size_t)rb * HD + col) = make_float2(o[nc][2], o[nc][3]);
  }
}

// ---------------------------------------------------------------------------
extern "C" void kernel_launch(void* const* d_in, const int* in_sizes, int n_in,
                              void* d_out, int out_size) {
  const float* x     = (const float*)d_in[0];
  const int*   eidx  = (const int*)d_in[1];
  const int*   etype = (const int*)d_in[2];
  const float* etime = (const float*)d_in[3];
  const float* fW    = (const float*)d_in[4];
  const float* fb    = (const float*)d_in[5];
  const float* rW1   = (const float*)d_in[6];
  const float* rb1   = (const float*)d_in[7];
  const float* rW2   = (const float*)d_in[8];
  const float* rb2   = (const float*)d_in[9];
  const float* oW0   = (const float*)d_in[10];
  const float* ob0   = (const float*)d_in[11];
  const float* oW1   = (const float*)d_in[12];
  const float* ob1   = (const float*)d_in[13];
  const float* oW2   = (const float*)d_in[14];
  const float* ob2   = (const float*)d_in[15];
  const float* lam   = (const float*)d_in[16];
  const float* beta  = (const float*)d_in[17];
  float* out = (float*)d_out;

  const int WB = (NN * 32 + 255) / 256;   // one warp per node
  dim3 gt2(TBX, 10);

  cudaFuncSetAttribute(k_pre, cudaFuncAttributeMaxDynamicSharedMemorySize, TRANS_SMEM);
  cudaFuncSetAttribute(k_mid, cudaFuncAttributeMaxDynamicSharedMemorySize, TRANS_SMEM);
  cudaFuncSetAttribute(k_trans2, cudaFuncAttributeMaxDynamicSharedMemorySize, TRANS_SMEM);
  cudaFuncSetAttribute(k_out_mma, cudaFuncAttributeMaxDynamicSharedMemorySize, TRANS_SMEM);

  // Zero S/deg via graph-capturable memset nodes.
  void *pS = nullptr, *pDeg = nullptr;
  cudaGetSymbolAddress(&pS, g_S);
  cudaGetSymbolAddress(&pDeg, g_deg);
  cudaMemsetAsync(pS, 0, NN * NR * sizeof(float));
  cudaMemsetAsync(pDeg, 0, NN * sizeof(int));

  // histwS || emb0
  k_pre<<<HB + TBX, 256, TRANS_SMEM>>>(etime, eidx, etype, lam, beta, x, fW, fb);
  k_scanA<<<NCHUNK, 256>>>();
  k_scanB<<<1, 256>>>();
  k_scanC<<<NCHUNK, 256>>>();

  // fill || trans layer-1
  k_mid<<<HB + 10 * TBX, 256, TRANS_SMEM>>>(eidx, etype, etime, lam, beta, rW1);
  k_edge_csr<<<WB, 256>>>(rb1, 0);

  // layer 2
  k_trans2<<<gt2, 256, TRANS_SMEM>>>(rW2);
  k_edge_csr<<<WB, 256>>>(rb2, 1);

  k_out_mma<<<TBX, 256, TRANS_SMEM>>>(oW0, ob0, oW1, ob1, oW2, ob2, out);
}

// round 16
// speedup vs baseline: 1.0347x; 1.0347x over previous
#include <cuda_runtime.h>
#include <cuda_fp16.h>
#include <cstdint>

#define NN 50000
#define NE 1600000
#define IND 128
#define HD 64
#define NR 5
#define SA_STRIDE 68
#define NEG_SLOPE 0.01f
#define NCHUNK 196   // ceil(50000/256)
#define TBX 391      // ceil(50000/128) tensor row tiles
#define HB 1563      // ceil(NE/1024) hist/fill blocks (4 edges/thread)

// ---- scratch (device globals; no allocation allowed) ----
__device__ float g_S[NN * NR];
__device__ int   g_deg[NN];
__device__ int   g_off[NN + 1];
__device__ int   g_part[256];
__device__ int   g_cur[NN];
__device__ int2  g_cpack[NE];     // {src | (r<<16), bits(w)}
__device__ float g_emb0[NN * HD];
__device__ float g_emb1[NN * HD];
__device__ float g_emb2[NN * HD];
__device__ __half g_T[(size_t)10 * NN * HD];  // fp16: TA_r (0..4), TB_r (5+r); 64 MB

// ---------------------------------------------------------------------------
// tf32 helpers (validated R3/R8)
__device__ __forceinline__ uint32_t f2tf(float f) {
  uint32_t r;
  asm("cvt.rna.tf32.f32 %0, %1;" : "=r"(r) : "f"(f));
  return r;
}
__device__ __forceinline__ void split_tf(float f, uint32_t& hi, uint32_t& lo) {
  hi = f2tf(f);
  lo = f2tf(f - __uint_as_float(hi));
}
__device__ __forceinline__ void mma_tf32(float c[4], uint32_t a0, uint32_t a1,
                                         uint32_t a2, uint32_t a3,
                                         uint32_t b0, uint32_t b1) {
  asm volatile(
      "mma.sync.aligned.m16n8k8.row.col.f32.tf32.tf32.f32 "
      "{%0,%1,%2,%3}, {%4,%5,%6,%7}, {%8,%9}, {%0,%1,%2,%3};"
      : "+f"(c[0]), "+f"(c[1]), "+f"(c[2]), "+f"(c[3])
      : "r"(a0), "r"(a1), "r"(a2), "r"(a3), "r"(b0), "r"(b1));
}

#define TRANS_SMEM (128 * SA_STRIDE * 4 + 8 * 8 * 32 * 16)  // 67584

// Shared tile routine (validated R8/R11).
__device__ __forceinline__ void tile_fill_mma(
    const float* __restrict__ Abase, int Kstride, int kofs, int row0,
    const float* __restrict__ W,
    float* sA, uint4* sBf, float acc[8][4],
    int tid, int lane, int warp) {
  int g = lane >> 2, tg = lane & 3;
  #pragma unroll 1
  for (int i = tid; i < 128 * 16; i += 256) {
    int r = i >> 4, c = i & 15;
    float4 v = make_float4(0.f, 0.f, 0.f, 0.f);
    if (row0 + r < NN)
      v = *(const float4*)(Abase + (size_t)(row0 + r) * Kstride + kofs + c * 4);
    *(float4*)(sA + r * SA_STRIDE + c * 4) = v;
  }
  #pragma unroll 1
  for (int s = tid; s < 8 * 8 * 32; s += 256) {
    int ks = s >> 8;
    int nc = (s >> 5) & 7;
    int ln = s & 31;
    int lg = ln >> 2, ltg = ln & 3;
    int k1 = ks * 8 + ltg, k2 = k1 + 4;
    int n = nc * 8 + lg;
    uint32_t h1, l1, h2, l2;
    split_tf(__ldg(&W[k1 * HD + n]), h1, l1);
    split_tf(__ldg(&W[k2 * HD + n]), h2, l2);
    sBf[s] = make_uint4(h1, h2, l1, l2);
  }
  __syncthreads();

  int wrow = warp * 16;
  #pragma unroll 1
  for (int ks = 0; ks < 8; ks++) {
    int kb = ks * 8;
    float af0 = sA[(wrow + g) * SA_STRIDE + kb + tg];
    float af1 = sA[(wrow + g + 8) * SA_STRIDE + kb + tg];
    float af2 = sA[(wrow + g) * SA_STRIDE + kb + tg + 4];
    float af3 = sA[(wrow + g + 8) * SA_STRIDE + kb + tg + 4];
    uint32_t ah0, al0, ah1, al1, ah2, al2, ah3, al3;
    split_tf(af0, ah0, al0);
    split_tf(af1, ah1, al1);
    split_tf(af2, ah2, al2);
    split_tf(af3, ah3, al3);
    const uint4* bp = sBf + ks * 8 * 32 + lane;
    #pragma unroll
    for (int nc = 0; nc < 8; nc++) {
      uint4 b = bp[nc * 32];
      mma_tf32(acc[nc], ah0, ah1, ah2, ah3, b.x, b.y);
      mma_tf32(acc[nc], ah0, ah1, ah2, ah3, b.z, b.w);
      mma_tf32(acc[nc], al0, al1, al2, al3, b.x, b.y);
    }
  }
}

// trans body: T[idx] = emb @ W_slice, fp16 writeback (validated R11).
__device__ __forceinline__ void trans_body(const float* __restrict__ relW,
                                           const float* __restrict__ emb,
                                           int idx, int bx, char* smraw) {
  float* sA = (float*)smraw;
  uint4* sBf = (uint4*)(smraw + 128 * SA_STRIDE * 4);
  int rr = idx % 5, half = idx / 5;
  const float* W = relW + ((size_t)rr * (2 * HD) + half * HD) * HD;

  int tid = threadIdx.x;
  int lane = tid & 31, warp = tid >> 5;
  int g = lane >> 2, tg = lane & 3;
  int row0 = bx * 128;

  float acc[8][4] = {};
  tile_fill_mma(emb, HD, 0, row0, W, sA, sBf, acc, tid, lane, warp);

  __half* out = g_T + (size_t)idx * NN * HD;
  int ra = row0 + warp * 16 + g;
  int rb = ra + 8;
  #pragma unroll
  for (int nc = 0; nc < 8; nc++) {
    int col = nc * 8 + 2 * tg;
    if (ra < NN)
      *(__half2*)(out + (size_t)ra * HD + col) = __floats2half2_rn(acc[nc][0], acc[nc][1]);
    if (rb < NN)
      *(__half2*)(out + (size_t)rb * HD + col) = __floats2half2_rn(acc[nc][2], acc[nc][3]);
  }
}

// ---------------------------------------------------------------------------
// K_pre: blocks [0,HB) -> edge histogram (4 edges/thread); [HB, HB+TBX) -> emb0.
__global__ void __launch_bounds__(256) k_pre(
    const float* __restrict__ etime, const int* __restrict__ eidx,
    const int* __restrict__ etype, const float* __restrict__ plam,
    const float* __restrict__ pbeta,
    const float* __restrict__ x, const float* __restrict__ fW,
    const float* __restrict__ fb) {
  extern __shared__ __align__(16) char smraw[];
  if (blockIdx.x < HB) {
    float lam = plam[0], beta = pbeta[0];
    int e0 = blockIdx.x * 1024 + threadIdx.x;
    #pragma unroll
    for (int k = 0; k < 4; k++) {
      int e = e0 + k * 256;
      if (e < NE) {
        float w = lam * expf(-beta * fabsf(__ldg(&etime[e])));
        int d = __ldg(&eidx[NE + e]);
        int r = __ldg(&etype[e]);
        atomicAdd(&g_S[d * NR + r], w);
        atomicAdd(&g_deg[d], 1);
      }
    }
    return;
  }
  // emb0 = x @ field_W + field_b (two k-halves)
  float* sA = (float*)smraw;
  uint4* sBf = (uint4*)(smraw + 128 * SA_STRIDE * 4);
  int tid = threadIdx.x;
  int lane = tid & 31, warp = tid >> 5;
  int g = lane >> 2, tg = lane & 3;
  int row0 = (blockIdx.x - HB) * 128;

  float acc[8][4] = {};
  tile_fill_mma(x, IND, 0, row0, fW, sA, sBf, acc, tid, lane, warp);
  __syncthreads();
  tile_fill_mma(x, IND, 64, row0, fW + (size_t)64 * HD, sA, sBf, acc, tid, lane, warp);

  int ra = row0 + warp * 16 + g;
  int rb = ra + 8;
  #pragma unroll
  for (int nc = 0; nc < 8; nc++) {
    int col = nc * 8 + 2 * tg;
    float b0 = __ldg(&fb[col]), b1 = __ldg(&fb[col + 1]);
    if (ra < NN)
      *(float2*)(g_emb0 + (size_t)ra * HD + col) =
          make_float2(acc[nc][0] + b0, acc[nc][1] + b1);
    if (rb < NN)
      *(float2*)(g_emb0 + (size_t)rb * HD + col) =
          make_float2(acc[nc][2] + b0, acc[nc][3] + b1);
  }
}

// ---------------------------------------------------------------------------
__global__ void k_scanA() {
  __shared__ int s[256];
  int tid = threadIdx.x;
  int i = blockIdx.x * 256 + tid;
  int v = (i < NN) ? g_deg[i] : 0;
  s[tid] = v;
  __syncthreads();
  #pragma unroll
  for (int d = 1; d < 256; d <<= 1) {
    int t = (tid >= d) ? s[tid - d] : 0;
    __syncthreads();
    s[tid] += t;
    __syncthreads();
  }
  if (i < NN) g_off[i] = s[tid] - v;
  if (tid == 255) g_part[blockIdx.x] = s[255];
}

__global__ void k_scanB() {
  __shared__ int s[256];
  int tid = threadIdx.x;
  int v = (tid < NCHUNK) ? g_part[tid] : 0;
  s[tid] = v;
  __syncthreads();
  #pragma unroll
  for (int d = 1; d < 256; d <<= 1) {
    int t = (tid >= d) ? s[tid - d] : 0;
    __syncthreads();
    s[tid] += t;
    __syncthreads();
  }
  if (tid < NCHUNK) g_part[tid] = s[tid] - v;
}

__global__ void k_scanC() {
  int i = blockIdx.x * 256 + threadIdx.x;
  if (i < NN) {
    int o = g_off[i] + g_part[i >> 8];
    g_off[i] = o;
    g_cur[i] = o;
  }
  if (i == 0) g_off[NN] = NE;
}

// ---------------------------------------------------------------------------
// K_mid: blocks [0,HB) -> CSR fill (4 edges/thread, int2 pack, recompute w);
//        blocks [HB, HB+10*TBX) -> trans layer-1 GEMMs.
__global__ void __launch_bounds__(256) k_mid(
    const int* __restrict__ eidx, const int* __restrict__ etype,
    const float* __restrict__ etime, const float* __restrict__ plam,
    const float* __restrict__ pbeta,
    const float* __restrict__ relW) {
  extern __shared__ __align__(16) char smraw[];
  if (blockIdx.x < HB) {
    float lam = plam[0], beta = pbeta[0];
    int e0 = blockIdx.x * 1024 + threadIdx.x;
    #pragma unroll
    for (int k = 0; k < 4; k++) {
      int e = e0 + k * 256;
      if (e < NE) {
        int d = __ldg(&eidx[NE + e]);
        float w = lam * expf(-beta * fabsf(__ldg(&etime[e])));
        int pos = atomicAdd(&g_cur[d], 1);
        g_cpack[pos] = make_int2(__ldg(&eidx[e]) | (__ldg(&etype[e]) << 16),
                                 __float_as_int(w));
      }
    }
    return;
  }
  int t = blockIdx.x - HB;
  trans_body(relW, g_emb0, t / TBX, t % TBX, smraw);
}

// Layer-2 trans (no merge partner).
__global__ void __launch_bounds__(256) k_trans2(const float* __restrict__ relW) {
  extern __shared__ __align__(16) char smraw[];
  trans_body(relW, g_emb1, blockIdx.y, blockIdx.x, smraw);
}

// ---------------------------------------------------------------------------
// CSR edge pass fused with dst-term (one warp/node, fp16 gathers, int2 meta).
// 2 edge-groups x 16 lanes x 8 B (measured local optimum).
__global__ void __launch_bounds__(256) k_edge_csr(const float* __restrict__ relb, int layer) {
  int node = (blockIdx.x * 256 + threadIdx.x) >> 5;
  if (node >= NN) return;
  int lane = threadIdx.x & 31;
  int grp = lane >> 4, fl = lane & 15;

  int beg = __ldg(&g_off[node]);
  int end = __ldg(&g_off[node + 1]);

  float4 a = make_float4(0.f, 0.f, 0.f, 0.f);
  #pragma unroll 4
  for (int j = beg + grp; j < end; j += 2) {
    int2 p = __ldg(&g_cpack[j]);
    int src = p.x & 0xFFFF;
    int r = p.x >> 16;
    float w = __int_as_float(p.y);
    const uint2* rowp = (const uint2*)(g_T + ((size_t)r * NN + src) * HD);
    uint2 raw = __ldg(rowp + fl);
    float2 f0 = __half22float2(*(__half2*)&raw.x);
    float2 f1 = __half22float2(*(__half2*)&raw.y);
    a.x += w * f0.x; a.y += w * f0.y; a.z += w * f1.x; a.w += w * f1.y;
  }
  a.x += __shfl_xor_sync(0xFFFFFFFF, a.x, 16);
  a.y += __shfl_xor_sync(0xFFFFFFFF, a.y, 16);
  a.z += __shfl_xor_sync(0xFFFFFFFF, a.z, 16);
  a.w += __shfl_xor_sync(0xFFFFFFFF, a.w, 16);

  if (grp == 0) {
    #pragma unroll
    for (int r = 0; r < NR; r++) {
      float s = __ldg(&g_S[node * NR + r]);
      const uint2* tp = (const uint2*)(g_T + ((size_t)(5 + r) * NN + node) * HD);
      uint2 raw = __ldg(tp + fl);
      float2 t0 = __half22float2(*(__half2*)&raw.x);
      float2 t1 = __half22float2(*(__half2*)&raw.y);
      float4 b4 = __ldg((const float4*)(relb + r * HD) + fl);
      a.x += s * (t0.x + b4.x);
      a.y += s * (t0.y + b4.y);
      a.z += s * (t1.x + b4.z);
      a.w += s * (t1.y + b4.w);
    }
    float* emb = (layer == 0) ? g_emb1 : g_emb2;
    *(float4*)(emb + (size_t)node * HD + fl * 4) = a;
  }
}

// out = sum_j leaky_relu(emb_j @ outW_j + outb_j), fused j-loop.
__global__ void __launch_bounds__(256) k_out_mma(
    const float* __restrict__ W0, const float* __restrict__ b0,
    const float* __restrict__ W1, const float* __restrict__ b1,
    const float* __restrict__ W2, const float* __restrict__ b2,
    float* __restrict__ out) {
  extern __shared__ __align__(16) char smraw[];
  float* sA = (float*)smraw;
  uint4* sBf = (uint4*)(smraw + 128 * SA_STRIDE * 4);

  int tid = threadIdx.x;
  int lane = tid & 31, warp = tid >> 5;
  int g = lane >> 2, tg = lane & 3;
  int row0 = blockIdx.x * 128;

  float o[8][4] = {};
  #pragma unroll 1
  for (int j = 0; j < 3; j++) {
    const float* emb = (j == 0) ? g_emb0 : (j == 1) ? g_emb1 : g_emb2;
    const float* W = (j == 0) ? W0 : (j == 1) ? W1 : W2;
    const float* b = (j == 0) ? b0 : (j == 1) ? b1 : b2;
    if (j) __syncthreads();
    float acc[8][4] = {};
    tile_fill_mma(emb, HD, 0, row0, W, sA, sBf, acc, tid, lane, warp);
    #pragma unroll
    for (int nc = 0; nc < 8; nc++) {
      int col = nc * 8 + 2 * tg;
      float bb0 = __ldg(&b[col]), bb1 = __ldg(&b[col + 1]);
      float z;
      z = acc[nc][0] + bb0; o[nc][0] += (z >= 0.f) ? z : NEG_SLOPE * z;
      z = acc[nc][1] + bb1; o[nc][1] += (z >= 0.f) ? z : NEG_SLOPE * z;
      z = acc[nc][2] + bb0; o[nc][2] += (z >= 0.f) ? z : NEG_SLOPE * z;
      z = acc[nc][3] + bb1; o[nc][3] += (z >= 0.f) ? z : NEG_SLOPE * z;
    }
  }

  int ra = row0 + warp * 16 + g;
  int rb = ra + 8;
  #pragma unroll
  for (int nc = 0; nc < 8; nc++) {
    int col = nc * 8 + 2 * tg;
    if (ra < NN)
      *(float2*)(out + (size_t)ra * HD + col) = make_float2(o[nc][0], o[nc][1]);
    if (rb < NN)
      *(float2*)(out + (size_t)rb * HD + col) = make_float2(o[nc][2], o[nc][3]);
  }
}

// ---------------------------------------------------------------------------
extern "C" void kernel_launch(void* const* d_in, const int* in_sizes, int n_in,
                              void* d_out, int out_size) {
  const float* x     = (const float*)d_in[0];
  const int*   eidx  = (const int*)d_in[1];
  const int*   etype = (const int*)d_in[2];
  const float* etime = (const float*)d_in[3];
  const float* fW    = (const float*)d_in[4];
  const float* fb    = (const float*)d_in[5];
  const float* rW1   = (const float*)d_in[6];
  const float* rb1   = (const float*)d_in[7];
  const float* rW2   = (const float*)d_in[8];
  const float* rb2   = (const float*)d_in[9];
  const float* oW0   = (const float*)d_in[10];
  const float* ob0   = (const float*)d_in[11];
  const float* oW1   = (const float*)d_in[12];
  const float* ob1   = (const float*)d_in[13];
  const float* oW2   = (const float*)d_in[14];
  const float* ob2   = (const float*)d_in[15];
  const float* lam   = (const float*)d_in[16];
  const float* beta  = (const float*)d_in[17];
  float* out = (float*)d_out;

  const int WB = (NN * 32 + 255) / 256;   // one warp per node
  dim3 gt2(TBX, 10);

  cudaFuncSetAttribute(k_pre, cudaFuncAttributeMaxDynamicSharedMemorySize, TRANS_SMEM);
  cudaFuncSetAttribute(k_mid, cudaFuncAttributeMaxDynamicSharedMemorySize, TRANS_SMEM);
  cudaFuncSetAttribute(k_trans2, cudaFuncAttributeMaxDynamicSharedMemorySize, TRANS_SMEM);
  cudaFuncSetAttribute(k_out_mma, cudaFuncAttributeMaxDynamicSharedMemorySize, TRANS_SMEM);

  // Zero S/deg via graph-capturable memset nodes.
  void *pS = nullptr, *pDeg = nullptr;
  cudaGetSymbolAddress(&pS, g_S);
  cudaGetSymbolAddress(&pDeg, g_deg);
  cudaMemsetAsync(pS, 0, NN * NR * sizeof(float));
  cudaMemsetAsync(pDeg, 0, NN * sizeof(int));

  // histwS || emb0
  k_pre<<<HB + TBX, 256, TRANS_SMEM>>>(etime, eidx, etype, lam, beta, x, fW, fb);
  k_scanA<<<NCHUNK, 256>>>();
  k_scanB<<<1, 256>>>();
  k_scanC<<<NCHUNK, 256>>>();

  // fill || trans layer-1
  k_mid<<<HB + 10 * TBX, 256, TRANS_SMEM>>>(eidx, etype, etime, lam, beta, rW1);
  k_edge_csr<<<WB, 256>>>(rb1, 0);

  // layer 2
  k_trans2<<<gt2, 256, TRANS_SMEM>>>(rW2);
  k_edge_csr<<<WB, 256>>>(rb2, 1);

  k_out_mma<<<TBX, 256, TRANS_SMEM>>>(oW0, ob0, oW1, ob1, oW2, ob2, out);
}

// round 17
// speedup vs baseline: 1.0947x; 1.0579x over previous
#include <cuda_runtime.h>
#include <cuda_fp16.h>
#include <cstdint>

#define NN 50000
#define NE 1600000
#define IND 128
#define HD 64
#define NR 5
#define SA_STRIDE 68
#define SAH_STRIDE 68   // halves
#define NEG_SLOPE 0.01f
#define NCHUNK 196   // ceil(50000/256)
#define TBX 391      // ceil(50000/128) tensor row tiles
#define HB 1563      // ceil(NE/1024) hist/fill blocks (4 edges/thread)

// ---- scratch (device globals; no allocation allowed) ----
__device__ float g_S[NN * NR];
__device__ int   g_deg[NN];
__device__ int   g_off[NN + 1];
__device__ int   g_part[256];
__device__ int   g_cur[NN];
__device__ int2  g_cpack[NE];     // {src | (r<<16), bits(w)}
__device__ float g_emb0[NN * HD];
__device__ float g_emb1[NN * HD];
__device__ float g_emb2[NN * HD];
__device__ __half g_T[(size_t)10 * NN * HD];  // fp16: TA_r (0..4), TB_r (5+r); 64 MB

// ---------------------------------------------------------------------------
// tf32 helpers (validated R3/R8)
__device__ __forceinline__ uint32_t f2tf(float f) {
  uint32_t r;
  asm("cvt.rna.tf32.f32 %0, %1;" : "=r"(r) : "f"(f));
  return r;
}
__device__ __forceinline__ void split_tf(float f, uint32_t& hi, uint32_t& lo) {
  hi = f2tf(f);
  lo = f2tf(f - __uint_as_float(hi));
}
__device__ __forceinline__ void mma_tf32(float c[4], uint32_t a0, uint32_t a1,
                                         uint32_t a2, uint32_t a3,
                                         uint32_t b0, uint32_t b1) {
  asm volatile(
      "mma.sync.aligned.m16n8k8.row.col.f32.tf32.tf32.f32 "
      "{%0,%1,%2,%3}, {%4,%5,%6,%7}, {%8,%9}, {%0,%1,%2,%3};"
      : "+f"(c[0]), "+f"(c[1]), "+f"(c[2]), "+f"(c[3])
      : "r"(a0), "r"(a1), "r"(a2), "r"(a3), "r"(b0), "r"(b1));
}

#define TRANS_SMEM   (128 * SA_STRIDE * 4 + 8 * 8 * 32 * 16)   // 67584 (fp32-A path)
#define TRANS_SMEM_H (128 * SAH_STRIDE * 2 + 8 * 8 * 32 * 16)  // 50176 (fp16-A path)

// B fragment pre-split (shared by both paths).
__device__ __forceinline__ void fill_sBf(const float* __restrict__ W, uint4* sBf, int tid) {
  #pragma unroll 1
  for (int s = tid; s < 8 * 8 * 32; s += 256) {
    int ks = s >> 8;
    int nc = (s >> 5) & 7;
    int ln = s & 31;
    int lg = ln >> 2, ltg = ln & 3;
    int k1 = ks * 8 + ltg, k2 = k1 + 4;
    int n = nc * 8 + lg;
    uint32_t h1, l1, h2, l2;
    split_tf(__ldg(&W[k1 * HD + n]), h1, l1);
    split_tf(__ldg(&W[k2 * HD + n]), h2, l2);
    sBf[s] = make_uint4(h1, h2, l1, l2);
  }
}

// Exact fp32-A tile routine (validated R8/R11): 3 mma per (ks,nc).
__device__ __forceinline__ void tile_fill_mma(
    const float* __restrict__ Abase, int Kstride, int kofs, int row0,
    const float* __restrict__ W,
    float* sA, uint4* sBf, float acc[8][4],
    int tid, int lane, int warp) {
  int g = lane >> 2, tg = lane & 3;
  #pragma unroll 1
  for (int i = tid; i < 128 * 16; i += 256) {
    int r = i >> 4, c = i & 15;
    float4 v = make_float4(0.f, 0.f, 0.f, 0.f);
    if (row0 + r < NN)
      v = *(const float4*)(Abase + (size_t)(row0 + r) * Kstride + kofs + c * 4);
    *(float4*)(sA + r * SA_STRIDE + c * 4) = v;
  }
  fill_sBf(W, sBf, tid);
  __syncthreads();

  int wrow = warp * 16;
  #pragma unroll 1
  for (int ks = 0; ks < 8; ks++) {
    int kb = ks * 8;
    float af0 = sA[(wrow + g) * SA_STRIDE + kb + tg];
    float af1 = sA[(wrow + g + 8) * SA_STRIDE + kb + tg];
    float af2 = sA[(wrow + g) * SA_STRIDE + kb + tg + 4];
    float af3 = sA[(wrow + g + 8) * SA_STRIDE + kb + tg + 4];
    uint32_t ah0, al0, ah1, al1, ah2, al2, ah3, al3;
    split_tf(af0, ah0, al0);
    split_tf(af1, ah1, al1);
    split_tf(af2, ah2, al2);
    split_tf(af3, ah3, al3);
    const uint4* bp = sBf + ks * 8 * 32 + lane;
    #pragma unroll
    for (int nc = 0; nc < 8; nc++) {
      uint4 b = bp[nc * 32];
      mma_tf32(acc[nc], ah0, ah1, ah2, ah3, b.x, b.y);
      mma_tf32(acc[nc], ah0, ah1, ah2, ah3, b.z, b.w);
      mma_tf32(acc[nc], al0, al1, al2, al3, b.x, b.y);
    }
  }
}

// fp16-A tile routine (trans path only): A rounded to fp16 in smem.
// fp16 -> tf32 is EXACT (11 sig bits each), so a_lo == 0 and only 2 mma
// per (ks,nc) are needed. smem: 17408 (A) + 32768 (Bf) = 50176 -> 4 blocks/SM.
__device__ __forceinline__ void tile_fill_mma_h(
    const float* __restrict__ Abase, int row0,
    const float* __restrict__ W,
    __half* sAh, uint4* sBf, float acc[8][4],
    int tid, int lane, int warp) {
  int g = lane >> 2, tg = lane & 3;
  #pragma unroll 1
  for (int i = tid; i < 128 * 16; i += 256) {
    int r = i >> 4, c = i & 15;
    float4 v = make_float4(0.f, 0.f, 0.f, 0.f);
    if (row0 + r < NN)
      v = *(const float4*)(Abase + (size_t)(row0 + r) * HD + c * 4);
    __half2 h0 = __floats2half2_rn(v.x, v.y);
    __half2 h1 = __floats2half2_rn(v.z, v.w);
    uint2 packed = make_uint2(*(uint32_t*)&h0, *(uint32_t*)&h1);
    *(uint2*)(sAh + r * SAH_STRIDE + c * 4) = packed;
  }
  fill_sBf(W, sBf, tid);
  __syncthreads();

  int wrow = warp * 16;
  #pragma unroll 1
  for (int ks = 0; ks < 8; ks++) {
    int kb = ks * 8;
    uint32_t ah0 = f2tf(__half2float(sAh[(wrow + g) * SAH_STRIDE + kb + tg]));
    uint32_t ah1 = f2tf(__half2float(sAh[(wrow + g + 8) * SAH_STRIDE + kb + tg]));
    uint32_t ah2 = f2tf(__half2float(sAh[(wrow + g) * SAH_STRIDE + kb + tg + 4]));
    uint32_t ah3 = f2tf(__half2float(sAh[(wrow + g + 8) * SAH_STRIDE + kb + tg + 4]));
    const uint4* bp = sBf + ks * 8 * 32 + lane;
    #pragma unroll
    for (int nc = 0; nc < 8; nc++) {
      uint4 b = bp[nc * 32];
      mma_tf32(acc[nc], ah0, ah1, ah2, ah3, b.x, b.y);  // a * b_hi
      mma_tf32(acc[nc], ah0, ah1, ah2, ah3, b.z, b.w);  // a * b_lo
    }
  }
}

// trans body: T[idx] = emb @ W_slice, fp16-A path, fp16 writeback.
__device__ __forceinline__ void trans_body(const float* __restrict__ relW,
                                           const float* __restrict__ emb,
                                           int idx, int bx, char* smraw) {
  __half* sAh = (__half*)smraw;
  uint4* sBf = (uint4*)(smraw + 128 * SAH_STRIDE * 2);
  int rr = idx % 5, half = idx / 5;
  const float* W = relW + ((size_t)rr * (2 * HD) + half * HD) * HD;

  int tid = threadIdx.x;
  int lane = tid & 31, warp = tid >> 5;
  int g = lane >> 2, tg = lane & 3;
  int row0 = bx * 128;

  float acc[8][4] = {};
  tile_fill_mma_h(emb, row0, W, sAh, sBf, acc, tid, lane, warp);

  __half* out = g_T + (size_t)idx * NN * HD;
  int ra = row0 + warp * 16 + g;
  int rb = ra + 8;
  #pragma unroll
  for (int nc = 0; nc < 8; nc++) {
    int col = nc * 8 + 2 * tg;
    if (ra < NN)
      *(__half2*)(out + (size_t)ra * HD + col) = __floats2half2_rn(acc[nc][0], acc[nc][1]);
    if (rb < NN)
      *(__half2*)(out + (size_t)rb * HD + col) = __floats2half2_rn(acc[nc][2], acc[nc][3]);
  }
}

// ---------------------------------------------------------------------------
// K_pre: blocks [0,HB) -> edge histogram (4 edges/thread); [HB, HB+TBX) -> emb0
// (emb0 keeps the exact fp32/3-mma path: its inputs feed everything downstream).
__global__ void __launch_bounds__(256) k_pre(
    const float* __restrict__ etime, const int* __restrict__ eidx,
    const int* __restrict__ etype, const float* __restrict__ plam,
    const float* __restrict__ pbeta,
    const float* __restrict__ x, const float* __restrict__ fW,
    const float* __restrict__ fb) {
  extern __shared__ __align__(16) char smraw[];
  if (blockIdx.x < HB) {
    float lam = plam[0], beta = pbeta[0];
    int e0 = blockIdx.x * 1024 + threadIdx.x;
    #pragma unroll
    for (int k = 0; k < 4; k++) {
      int e = e0 + k * 256;
      if (e < NE) {
        float w = lam * expf(-beta * fabsf(__ldg(&etime[e])));
        int d = __ldg(&eidx[NE + e]);
        int r = __ldg(&etype[e]);
        atomicAdd(&g_S[d * NR + r], w);
        atomicAdd(&g_deg[d], 1);
      }
    }
    return;
  }
  float* sA = (float*)smraw;
  uint4* sBf = (uint4*)(smraw + 128 * SA_STRIDE * 4);
  int tid = threadIdx.x;
  int lane = tid & 31, warp = tid >> 5;
  int g = lane >> 2, tg = lane & 3;
  int row0 = (blockIdx.x - HB) * 128;

  float acc[8][4] = {};
  tile_fill_mma(x, IND, 0, row0, fW, sA, sBf, acc, tid, lane, warp);
  __syncthreads();
  tile_fill_mma(x, IND, 64, row0, fW + (size_t)64 * HD, sA, sBf, acc, tid, lane, warp);

  int ra = row0 + warp * 16 + g;
  int rb = ra + 8;
  #pragma unroll
  for (int nc = 0; nc < 8; nc++) {
    int col = nc * 8 + 2 * tg;
    float b0 = __ldg(&fb[col]), b1 = __ldg(&fb[col + 1]);
    if (ra < NN)
      *(float2*)(g_emb0 + (size_t)ra * HD + col) =
          make_float2(acc[nc][0] + b0, acc[nc][1] + b1);
    if (rb < NN)
      *(float2*)(g_emb0 + (size_t)rb * HD + col) =
          make_float2(acc[nc][2] + b0, acc[nc][3] + b1);
  }
}

// ---------------------------------------------------------------------------
__global__ void k_scanA() {
  __shared__ int s[256];
  int tid = threadIdx.x;
  int i = blockIdx.x * 256 + tid;
  int v = (i < NN) ? g_deg[i] : 0;
  s[tid] = v;
  __syncthreads();
  #pragma unroll
  for (int d = 1; d < 256; d <<= 1) {
    int t = (tid >= d) ? s[tid - d] : 0;
    __syncthreads();
    s[tid] += t;
    __syncthreads();
  }
  if (i < NN) g_off[i] = s[tid] - v;
  if (tid == 255) g_part[blockIdx.x] = s[255];
}

__global__ void k_scanB() {
  __shared__ int s[256];
  int tid = threadIdx.x;
  int v = (tid < NCHUNK) ? g_part[tid] : 0;
  s[tid] = v;
  __syncthreads();
  #pragma unroll
  for (int d = 1; d < 256; d <<= 1) {
    int t = (tid >= d) ? s[tid - d] : 0;
    __syncthreads();
    s[tid] += t;
    __syncthreads();
  }
  if (tid < NCHUNK) g_part[tid] = s[tid] - v;
}

__global__ void k_scanC() {
  int i = blockIdx.x * 256 + threadIdx.x;
  if (i < NN) {
    int o = g_off[i] + g_part[i >> 8];
    g_off[i] = o;
    g_cur[i] = o;
  }
  if (i == 0) g_off[NN] = NE;
}

// ---------------------------------------------------------------------------
// K_mid: blocks [0,HB) -> CSR fill (4 edges/thread, int2 pack, recompute w);
//        blocks [HB, HB+10*TBX) -> trans layer-1 GEMMs (fp16-A path).
__global__ void __launch_bounds__(256) k_mid(
    const int* __restrict__ eidx, const int* __restrict__ etype,
    const float* __restrict__ etime, const float* __restrict__ plam,
    const float* __restrict__ pbeta,
    const float* __restrict__ relW) {
  extern __shared__ __align__(16) char smraw[];
  if (blockIdx.x < HB) {
    float lam = plam[0], beta = pbeta[0];
    int e0 = blockIdx.x * 1024 + threadIdx.x;
    #pragma unroll
    for (int k = 0; k < 4; k++) {
      int e = e0 + k * 256;
      if (e < NE) {
        int d = __ldg(&eidx[NE + e]);
        float w = lam * expf(-beta * fabsf(__ldg(&etime[e])));
        int pos = atomicAdd(&g_cur[d], 1);
        g_cpack[pos] = make_int2(__ldg(&eidx[e]) | (__ldg(&etype[e]) << 16),
                                 __float_as_int(w));
      }
    }
    return;
  }
  int t = blockIdx.x - HB;
  trans_body(relW, g_emb0, t / TBX, t % TBX, smraw);
}

// Layer-2 trans (no merge partner).
__global__ void __launch_bounds__(256) k_trans2(const float* __restrict__ relW) {
  extern __shared__ __align__(16) char smraw[];
  trans_body(relW, g_emb1, blockIdx.y, blockIdx.x, smraw);
}

// ---------------------------------------------------------------------------
// CSR edge pass fused with dst-term (one warp/node, fp16 gathers, int2 meta).
// 2 edge-groups x 16 lanes x 8 B (measured local optimum).
__global__ void __launch_bounds__(256) k_edge_csr(const float* __restrict__ relb, int layer) {
  int node = (blockIdx.x * 256 + threadIdx.x) >> 5;
  if (node >= NN) return;
  int lane = threadIdx.x & 31;
  int grp = lane >> 4, fl = lane & 15;

  int beg = __ldg(&g_off[node]);
  int end = __ldg(&g_off[node + 1]);

  float4 a = make_float4(0.f, 0.f, 0.f, 0.f);
  #pragma unroll 4
  for (int j = beg + grp; j < end; j += 2) {
    int2 p = __ldg(&g_cpack[j]);
    int src = p.x & 0xFFFF;
    int r = p.x >> 16;
    float w = __int_as_float(p.y);
    const uint2* rowp = (const uint2*)(g_T + ((size_t)r * NN + src) * HD);
    uint2 raw = __ldg(rowp + fl);
    float2 f0 = __half22float2(*(__half2*)&raw.x);
    float2 f1 = __half22float2(*(__half2*)&raw.y);
    a.x += w * f0.x; a.y += w * f0.y; a.z += w * f1.x; a.w += w * f1.y;
  }
  a.x += __shfl_xor_sync(0xFFFFFFFF, a.x, 16);
  a.y += __shfl_xor_sync(0xFFFFFFFF, a.y, 16);
  a.z += __shfl_xor_sync(0xFFFFFFFF, a.z, 16);
  a.w += __shfl_xor_sync(0xFFFFFFFF, a.w, 16);

  if (grp == 0) {
    #pragma unroll
    for (int r = 0; r < NR; r++) {
      float s = __ldg(&g_S[node * NR + r]);
      const uint2* tp = (const uint2*)(g_T + ((size_t)(5 + r) * NN + node) * HD);
      uint2 raw = __ldg(tp + fl);
      float2 t0 = __half22float2(*(__half2*)&raw.x);
      float2 t1 = __half22float2(*(__half2*)&raw.y);
      float4 b4 = __ldg((const float4*)(relb + r * HD) + fl);
      a.x += s * (t0.x + b4.x);
      a.y += s * (t0.y + b4.y);
      a.z += s * (t1.x + b4.z);
      a.w += s * (t1.y + b4.w);
    }
    float* emb = (layer == 0) ? g_emb1 : g_emb2;
    *(float4*)(emb + (size_t)node * HD + fl * 4) = a;
  }
}

// out = sum_j leaky_relu(emb_j @ outW_j + outb_j), fused j-loop (exact fp32 path).
__global__ void __launch_bounds__(256) k_out_mma(
    const float* __restrict__ W0, const float* __restrict__ b0,
    const float* __restrict__ W1, const float* __restrict__ b1,
    const float* __restrict__ W2, const float* __restrict__ b2,
    float* __restrict__ out) {
  extern __shared__ __align__(16) char smraw[];
  float* sA = (float*)smraw;
  uint4* sBf = (uint4*)(smraw + 128 * SA_STRIDE * 4);

  int tid = threadIdx.x;
  int lane = tid & 31, warp = tid >> 5;
  int g = lane >> 2, tg = lane & 3;
  int row0 = blockIdx.x * 128;

  float o[8][4] = {};
  #pragma unroll 1
  for (int j = 0; j < 3; j++) {
    const float* emb = (j == 0) ? g_emb0 : (j == 1) ? g_emb1 : g_emb2;
    const float* W = (j == 0) ? W0 : (j == 1) ? W1 : W2;
    const float* b = (j == 0) ? b0 : (j == 1) ? b1 : b2;
    if (j) __syncthreads();
    float acc[8][4] = {};
    tile_fill_mma(emb, HD, 0, row0, W, sA, sBf, acc, tid, lane, warp);
    #pragma unroll
    for (int nc = 0; nc < 8; nc++) {
      int col = nc * 8 + 2 * tg;
      float bb0 = __ldg(&b[col]), bb1 = __ldg(&b[col + 1]);
      float z;
      z = acc[nc][0] + bb0; o[nc][0] += (z >= 0.f) ? z : NEG_SLOPE * z;
      z = acc[nc][1] + bb1; o[nc][1] += (z >= 0.f) ? z : NEG_SLOPE * z;
      z = acc[nc][2] + bb0; o[nc][2] += (z >= 0.f) ? z : NEG_SLOPE * z;
      z = acc[nc][3] + bb1; o[nc][3] += (z >= 0.f) ? z : NEG_SLOPE * z;
    }
  }

  int ra = row0 + warp * 16 + g;
  int rb = ra + 8;
  #pragma unroll
  for (int nc = 0; nc < 8; nc++) {
    int col = nc * 8 + 2 * tg;
    if (ra < NN)
      *(float2*)(out + (size_t)ra * HD + col) = make_float2(o[nc][0], o[nc][1]);
    if (rb < NN)
      *(float2*)(out + (size_t)rb * HD + col) = make_float2(o[nc][2], o[nc][3]);
  }
}

// ---------------------------------------------------------------------------
extern "C" void kernel_launch(void* const* d_in, const int* in_sizes, int n_in,
                              void* d_out, int out_size) {
  const float* x     = (const float*)d_in[0];
  const int*   eidx  = (const int*)d_in[1];
  const int*   etype = (const int*)d_in[2];
  const float* etime = (const float*)d_in[3];
  const float* fW    = (const float*)d_in[4];
  const float* fb    = (const float*)d_in[5];
  const float* rW1   = (const float*)d_in[6];
  const float* rb1   = (const float*)d_in[7];
  const float* rW2   = (const float*)d_in[8];
  const float* rb2   = (const float*)d_in[9];
  const float* oW0   = (const float*)d_in[10];
  const float* ob0   = (const float*)d_in[11];
  const float* oW1   = (const float*)d_in[12];
  const float* ob1   = (const float*)d_in[13];
  const float* oW2   = (const float*)d_in[14];
  const float* ob2   = (const float*)d_in[15];
  const float* lam   = (const float*)d_in[16];
  const float* beta  = (const float*)d_in[17];
  float* out = (float*)d_out;

  const int WB = (NN * 32 + 255) / 256;   // one warp per node
  dim3 gt2(TBX, 10);

  cudaFuncSetAttribute(k_pre, cudaFuncAttributeMaxDynamicSharedMemorySize, TRANS_SMEM);
  cudaFuncSetAttribute(k_mid, cudaFuncAttributeMaxDynamicSharedMemorySize, TRANS_SMEM_H);
  cudaFuncSetAttribute(k_trans2, cudaFuncAttributeMaxDynamicSharedMemorySize, TRANS_SMEM_H);
  cudaFuncSetAttribute(k_out_mma, cudaFuncAttributeMaxDynamicSharedMemorySize, TRANS_SMEM);

  // Zero S/deg via graph-capturable memset nodes.
  void *pS = nullptr, *pDeg = nullptr;
  cudaGetSymbolAddress(&pS, g_S);
  cudaGetSymbolAddress(&pDeg, g_deg);
  cudaMemsetAsync(pS, 0, NN * NR * sizeof(float));
  cudaMemsetAsync(pDeg, 0, NN * sizeof(int));

  // histwS || emb0
  k_pre<<<HB + TBX, 256, TRANS_SMEM>>>(etime, eidx, etype, lam, beta, x, fW, fb);
  k_scanA<<<NCHUNK, 256>>>();
  k_scanB<<<1, 256>>>();
  k_scanC<<<NCHUNK, 256>>>();

  // fill || trans layer-1 (fp16-A path, 4 blocks/SM)
  k_mid<<<HB + 10 * TBX, 256, TRANS_SMEM_H>>>(eidx, etype, etime, lam, beta, rW1);
  k_edge_csr<<<WB, 256>>>(rb1, 0);

  // layer 2
  k_trans2<<<gt2, 256, TRANS_SMEM_H>>>(rW2);
  k_edge_csr<<<WB, 256>>>(rb2, 1);

  k_out_mma<<<TBX, 256, TRANS_SMEM>>>(oW0, ob0, oW1, ob1, oW2, ob2, out);
}